// round 2
// baseline (speedup 1.0000x reference)
#include <cuda_runtime.h>
#include <cuda_bf16.h>
#include <math.h>

// Problem constants
#define BB   512
#define NN   101
#define EE   128
#define MM   8
#define DKK  16
#define TT   (BB * NN)        // 51712 tokens, divisible by 64 (808*64)
#define FF   (4 * EE)         // 512
#define EPS  1e-5f

// ---------------- device scratch (no allocations allowed) ----------------
__device__ float g_x[TT * EE];
__device__ float g_q[TT * EE];
__device__ float g_k[TT * EE];
__device__ float g_v[TT * EE];
__device__ float g_o[TT * EE];
__device__ float g_t[TT * EE];
__device__ float g_h[TT * FF];
__device__ float g_ps [128 * EE];
__device__ float g_ps2[128 * EE];
__device__ float g_mean[EE];
__device__ float g_istd[EE];

// ---------------- embedding ----------------
// node = cat(s, d) @ e_w + e_b ; row n==0 uses s @ ep_w + ep_b
__global__ void embed_kernel(const float* __restrict__ s, const int* __restrict__ d,
                             const float* __restrict__ e_w, const float* __restrict__ e_b,
                             const float* __restrict__ ep_w, const float* __restrict__ ep_b,
                             float* __restrict__ x)
{
    int idx = blockIdx.x * 256 + threadIdx.x;
    if (idx >= TT * EE) return;
    int e = idx & (EE - 1);
    int t = idx >> 7;
    int n = t % NN;
    int b = t / NN;
    float s0 = s[(b * NN + n) * 2 + 0];
    float s1 = s[(b * NN + n) * 2 + 1];
    float out;
    if (n == 0) {
        out = s0 * ep_w[e] + s1 * ep_w[EE + e] + ep_b[e];
    } else {
        float dd = (float)d[b * NN + n];
        out = s0 * e_w[e] + s1 * e_w[EE + e] + dd * e_w[2 * EE + e] + e_b[e];
    }
    x[idx] = out;
}

// ---------------- tiled fp32 GEMM with fused epilogue ----------------
// C[T,Nout] = A[T,K] @ W[K,Nout] + bias ; mode 0: none, 1: +res, 2: relu
#define Bb 64
#define Kb 32
__global__ __launch_bounds__(256) void gemm_ep(
    const float* __restrict__ A, const float* __restrict__ W,
    const float* __restrict__ bias, const float* __restrict__ res,
    float* __restrict__ C, int K, int Nout, int mode)
{
    const int t0 = blockIdx.y * Bb;
    const int n0 = blockIdx.x * Bb;
    __shared__ float As[Kb][Bb + 1];   // [k][m], padded
    __shared__ float Bs[Kb][Bb];       // [k][n]
    const int tid = threadIdx.x;
    const int tx = tid & 15;   // N micro-tile
    const int ty = tid >> 4;   // M micro-tile
    float acc[4][4] = {};

    for (int k0 = 0; k0 < K; k0 += Kb) {
        // A tile 64x32 -> transposed into As
        #pragma unroll
        for (int p = 0; p < 2; p++) {
            int i   = tid + p * 256;     // 0..511
            int row = i >> 3;            // 0..63
            int c4  = i & 7;             // 0..7
            float4 v4 = *reinterpret_cast<const float4*>(&A[(size_t)(t0 + row) * K + k0 + c4 * 4]);
            As[c4 * 4 + 0][row] = v4.x;
            As[c4 * 4 + 1][row] = v4.y;
            As[c4 * 4 + 2][row] = v4.z;
            As[c4 * 4 + 3][row] = v4.w;
        }
        // W tile 32x64
        #pragma unroll
        for (int p = 0; p < 2; p++) {
            int i   = tid + p * 256;
            int row = i >> 4;            // 0..31
            int c4  = i & 15;            // 0..15
            *reinterpret_cast<float4*>(&Bs[row][c4 * 4]) =
                *reinterpret_cast<const float4*>(&W[(size_t)(k0 + row) * Nout + n0 + c4 * 4]);
        }
        __syncthreads();
        #pragma unroll
        for (int kk = 0; kk < Kb; kk++) {
            float a[4];
            #pragma unroll
            for (int m = 0; m < 4; m++) a[m] = As[kk][ty * 4 + m];
            float4 b4 = *reinterpret_cast<const float4*>(&Bs[kk][tx * 4]);
            float bbv[4] = {b4.x, b4.y, b4.z, b4.w};
            #pragma unroll
            for (int m = 0; m < 4; m++)
                #pragma unroll
                for (int n = 0; n < 4; n++)
                    acc[m][n] += a[m] * bbv[n];
        }
        __syncthreads();
    }

    #pragma unroll
    for (int m = 0; m < 4; m++) {
        int row = t0 + ty * 4 + m;
        #pragma unroll
        for (int n = 0; n < 4; n++) {
            int col = n0 + tx * 4 + n;
            float v = acc[m][n] + bias[col];
            if (mode == 1)      v += res[(size_t)row * Nout + col];
            else if (mode == 2) v = fmaxf(v, 0.0f);
            C[(size_t)row * Nout + col] = v;
        }
    }
}

// ---------------- attention: one block per (batch, head) ----------------
__global__ __launch_bounds__(128) void attn_kernel(
    const float* __restrict__ Q, const float* __restrict__ K,
    const float* __restrict__ V, float* __restrict__ O)
{
    int bh = blockIdx.x;
    int b = bh >> 3;
    int h = bh & 7;
    const size_t base = (size_t)b * NN * EE + h * DKK;

    __shared__ float ksh[NN][DKK];
    __shared__ float vsh[NN][DKK];
    int tid = threadIdx.x;
    for (int i = tid; i < NN * DKK; i += 128) {
        int j = i >> 4, dd = i & 15;
        ksh[j][dd] = K[base + (size_t)j * EE + dd];
        vsh[j][dd] = V[base + (size_t)j * EE + dd];
    }
    __syncthreads();

    if (tid < NN) {
        float q[DKK];
        #pragma unroll
        for (int dd = 0; dd < DKK; dd++) q[dd] = Q[base + (size_t)tid * EE + dd];
        const float scale = 0.25f;  // 1/sqrt(16)

        float mmax = -1e30f;
        for (int j = 0; j < NN; j++) {
            float sdot = 0.f;
            #pragma unroll
            for (int dd = 0; dd < DKK; dd++) sdot += q[dd] * ksh[j][dd];
            mmax = fmaxf(mmax, sdot * scale);
        }
        float l = 0.f;
        float o[DKK];
        #pragma unroll
        for (int dd = 0; dd < DKK; dd++) o[dd] = 0.f;
        for (int j = 0; j < NN; j++) {
            float sdot = 0.f;
            #pragma unroll
            for (int dd = 0; dd < DKK; dd++) sdot += q[dd] * ksh[j][dd];
            float p = __expf(sdot * scale - mmax);
            l += p;
            #pragma unroll
            for (int dd = 0; dd < DKK; dd++) o[dd] += p * vsh[j][dd];
        }
        float inv = 1.0f / l;
        #pragma unroll
        for (int dd = 0; dd < DKK; dd++)
            O[base + (size_t)tid * EE + dd] = o[dd] * inv;
    }
}

// ---------------- BatchNorm: two-stage coalesced reduction ----------------
#define ROWS_PER_BLK (TT / 128)   // 404
__global__ __launch_bounds__(128) void bn_partial(const float* __restrict__ x,
                                                  float* __restrict__ psum,
                                                  float* __restrict__ psq)
{
    int e = threadIdx.x;
    int blk = blockIdx.x;
    int r0 = blk * ROWS_PER_BLK;
    float s = 0.f, s2 = 0.f;
    for (int r = 0; r < ROWS_PER_BLK; r++) {
        float v = x[(size_t)(r0 + r) * EE + e];
        s += v; s2 += v * v;
    }
    psum[blk * EE + e] = s;
    psq [blk * EE + e] = s2;
}

__global__ __launch_bounds__(128) void bn_finalize(const float* __restrict__ psum,
                                                   const float* __restrict__ psq,
                                                   float* __restrict__ mean,
                                                   float* __restrict__ istd)
{
    int e = threadIdx.x;
    float s = 0.f, s2 = 0.f;
    for (int i = 0; i < 128; i++) { s += psum[i * EE + e]; s2 += psq[i * EE + e]; }
    float mu = s / (float)TT;
    float var = s2 / (float)TT - mu * mu;
    mean[e] = mu;
    istd[e] = rsqrtf(var + EPS);
}

__global__ __launch_bounds__(256) void bn_apply(const float* __restrict__ x,
                                                const float* __restrict__ mean,
                                                const float* __restrict__ istd,
                                                const float* __restrict__ g,
                                                const float* __restrict__ be,
                                                float* __restrict__ y)
{
    int idx = blockIdx.x * 256 + threadIdx.x;
    if (idx >= TT * EE) return;
    int e = idx & (EE - 1);
    y[idx] = (x[idx] - mean[e]) * istd[e] * g[e] + be[e];
}

// ---------------- host orchestration ----------------
extern "C" void kernel_launch(void* const* d_in, const int* in_sizes, int n_in,
                              void* d_out, int out_size)
{
    const float* s    = (const float*)d_in[0];
    const int*   dd   = (const int*)  d_in[1];
    const float* e_w  = (const float*)d_in[2];
    const float* e_b  = (const float*)d_in[3];
    const float* ep_w = (const float*)d_in[4];
    const float* ep_b = (const float*)d_in[5];
    const float* Wq   = (const float*)d_in[6];
    const float* bq   = (const float*)d_in[7];
    const float* Wk   = (const float*)d_in[8];
    const float* bk   = (const float*)d_in[9];
    const float* Wv   = (const float*)d_in[10];
    const float* bv   = (const float*)d_in[11];
    const float* Wo   = (const float*)d_in[12];
    const float* bo   = (const float*)d_in[13];
    const float* Wf1  = (const float*)d_in[14];
    const float* bf1  = (const float*)d_in[15];
    const float* Wf2  = (const float*)d_in[16];
    const float* bf2  = (const float*)d_in[17];
    const float* g1   = (const float*)d_in[18];
    const float* be1  = (const float*)d_in[19];
    const float* g2   = (const float*)d_in[20];
    const float* be2  = (const float*)d_in[21];

    float *px, *pq, *pk, *pv, *po, *pt, *ph, *pps, *pps2, *pmean, *pistd;
    cudaGetSymbolAddress((void**)&px,    g_x);
    cudaGetSymbolAddress((void**)&pq,    g_q);
    cudaGetSymbolAddress((void**)&pk,    g_k);
    cudaGetSymbolAddress((void**)&pv,    g_v);
    cudaGetSymbolAddress((void**)&po,    g_o);
    cudaGetSymbolAddress((void**)&pt,    g_t);
    cudaGetSymbolAddress((void**)&ph,    g_h);
    cudaGetSymbolAddress((void**)&pps,   g_ps);
    cudaGetSymbolAddress((void**)&pps2,  g_ps2);
    cudaGetSymbolAddress((void**)&pmean, g_mean);
    cudaGetSymbolAddress((void**)&pistd, g_istd);

    const int elem_grid = (TT * EE) / 256;   // 25856
    const dim3 gE(EE / Bb, TT / Bb);         // (2, 808)
    const dim3 gF(FF / Bb, TT / Bb);         // (8, 808)

    embed_kernel<<<elem_grid, 256>>>(s, dd, e_w, e_b, ep_w, ep_b, px);

    for (int i = 0; i < 3; i++) {
        const float* Wqi = Wq + (size_t)i * EE * EE;
        const float* Wki = Wk + (size_t)i * EE * EE;
        const float* Wvi = Wv + (size_t)i * EE * EE;
        const float* Woi = Wo + (size_t)i * EE * EE;
        const float* W1i = Wf1 + (size_t)i * EE * FF;
        const float* W2i = Wf2 + (size_t)i * FF * EE;

        gemm_ep<<<gE, 256>>>(px, Wqi, bq + i * EE, nullptr, pq, EE, EE, 0);
        gemm_ep<<<gE, 256>>>(px, Wki, bk + i * EE, nullptr, pk, EE, EE, 0);
        gemm_ep<<<gE, 256>>>(px, Wvi, bv + i * EE, nullptr, pv, EE, EE, 0);

        attn_kernel<<<BB * MM, 128>>>(pq, pk, pv, po);

        // t = o @ Wo + bo + x
        gemm_ep<<<gE, 256>>>(po, Woi, bo + i * EE, px, pt, EE, EE, 1);
        bn_partial<<<128, 128>>>(pt, pps, pps2);
        bn_finalize<<<1, 128>>>(pps, pps2, pmean, pistd);
        bn_apply<<<elem_grid, 256>>>(pt, pmean, pistd, g1 + i * EE, be1 + i * EE, px);

        // h = relu(x @ Wf1 + bf1)
        gemm_ep<<<gF, 256>>>(px, W1i, bf1 + i * FF, nullptr, ph, EE, FF, 2);
        // t = h @ Wf2 + bf2 + x
        gemm_ep<<<gE, 256>>>(ph, W2i, bf2 + i * EE, px, pt, FF, EE, 1);
        bn_partial<<<128, 128>>>(pt, pps, pps2);
        bn_finalize<<<1, 128>>>(pps, pps2, pmean, pistd);
        float* outp = (i == 2) ? (float*)d_out : px;
        bn_apply<<<elem_grid, 256>>>(pt, pmean, pistd, g2 + i * EE, be2 + i * EE, outp);
    }
    (void)in_sizes; (void)n_in; (void)out_size;
}

// round 5
// speedup vs baseline: 1.1112x; 1.1112x over previous
#include <cuda_runtime.h>
#include <cuda_bf16.h>
#include <math.h>

// Problem constants
#define BB   512
#define NN   101
#define EE   128
#define MM   8
#define DKK  16
#define TT   (BB * NN)        // 51712 = 404 * 128
#define FF   (4 * EE)         // 512
#define QKV  (3 * EE)         // 384
#define EPS  1e-5f

// ---------------- device scratch ----------------
__device__ float g_x[TT * EE];
__device__ float g_qkv[TT * QKV];
__device__ float g_o[TT * EE];
__device__ float g_t[TT * EE];
__device__ float g_h[TT * FF];
__device__ float g_wqkv[3 * EE * QKV];
__device__ float g_bqkv[3 * QKV];
__device__ float g_ps [256 * EE];
__device__ float g_ps2[256 * EE];
__device__ float g_mean[EE];
__device__ float g_istd[EE];

// ---------------- f32x2 helpers ----------------
__device__ __forceinline__ unsigned long long fma2(unsigned long long a,
                                                   unsigned long long b,
                                                   unsigned long long c)
{
    unsigned long long d;
    asm("fma.rn.f32x2 %0, %1, %2, %3;" : "=l"(d) : "l"(a), "l"(b), "l"(c));
    return d;
}
__device__ __forceinline__ unsigned long long pack2(float x, float y)
{
    unsigned long long r;
    asm("mov.b64 %0, {%1, %2};" : "=l"(r) : "f"(x), "f"(y));
    return r;
}
__device__ __forceinline__ float2 unpack2(unsigned long long v)
{
    float2 r;
    asm("mov.b64 {%0, %1}, %2;" : "=f"(r.x), "=f"(r.y) : "l"(v));
    return r;
}

// ---------------- embedding ----------------
__global__ void embed_kernel(const float* __restrict__ s, const int* __restrict__ d,
                             const float* __restrict__ e_w, const float* __restrict__ e_b,
                             const float* __restrict__ ep_w, const float* __restrict__ ep_b,
                             float* __restrict__ x)
{
    int idx = blockIdx.x * 256 + threadIdx.x;
    if (idx >= TT * EE) return;
    int e = idx & (EE - 1);
    int t = idx >> 7;
    int n = t % NN;
    int b = t / NN;
    float s0 = s[(b * NN + n) * 2 + 0];
    float s1 = s[(b * NN + n) * 2 + 1];
    float out;
    if (n == 0) {
        out = s0 * ep_w[e] + s1 * ep_w[EE + e] + ep_b[e];
    } else {
        float dd = (float)d[b * NN + n];
        out = s0 * e_w[e] + s1 * e_w[EE + e] + dd * e_w[2 * EE + e] + e_b[e];
    }
    x[idx] = out;
}

// ---------------- pack QKV weights into one [E,384] matrix per layer ----------------
__global__ void pack_qkv(const float* __restrict__ Wq, const float* __restrict__ Wk,
                         const float* __restrict__ Wv, const float* __restrict__ bq,
                         const float* __restrict__ bk, const float* __restrict__ bv,
                         float* __restrict__ wout, float* __restrict__ bout)
{
    int idx = blockIdx.x * 256 + threadIdx.x;
    int total = 3 * EE * QKV;
    if (idx < total) {
        int i = idx / (EE * QKV);
        int r = idx % (EE * QKV);
        int k = r / QKV;
        int j = r % QKV;
        float v;
        if (j < EE)            v = Wq[(size_t)i * EE * EE + k * EE + j];
        else if (j < 2 * EE)   v = Wk[(size_t)i * EE * EE + k * EE + (j - EE)];
        else                   v = Wv[(size_t)i * EE * EE + k * EE + (j - 2 * EE)];
        wout[idx] = v;
    }
    if (idx < 3 * QKV) {
        int i = idx / QKV;
        int j = idx % QKV;
        float v;
        if (j < EE)            v = bq[i * EE + j];
        else if (j < 2 * EE)   v = bk[i * EE + (j - EE)];
        else                   v = bv[i * EE + (j - 2 * EE)];
        bout[idx] = v;
    }
}

// ---------------- 128x128-tile fp32 GEMM, f32x2 inner loop ----------------
// C[T,Nout] = A[T,K] @ W[K,Nout] + bias ; mode 0: none, 1: +res, 2: relu
#define BMt 128
#define BKt 32
#define APAD 4
__global__ __launch_bounds__(256, 2) void gemm_ep(
    const float* __restrict__ A, const float* __restrict__ W,
    const float* __restrict__ bias, const float* __restrict__ res,
    float* __restrict__ C, int K, int Nout, int mode)
{
    const int t0 = blockIdx.y * BMt;
    const int n0 = blockIdx.x * BMt;
    __shared__ float As[BKt][BMt + APAD];   // transposed [k][m]
    __shared__ float Bs[BKt][BMt];          // [k][n]
    const int tid = threadIdx.x;
    const int tx = tid & 15;
    const int ty = tid >> 4;

    unsigned long long acc[2][4][4];
    #pragma unroll
    for (int mq = 0; mq < 2; mq++)
        #pragma unroll
        for (int m = 0; m < 4; m++)
            #pragma unroll
            for (int p = 0; p < 4; p++)
                acc[mq][m][p] = pack2(0.f, 0.f);

    for (int k0 = 0; k0 < K; k0 += BKt) {
        // A tile: 128 rows x 32 k, transposed into As
        #pragma unroll
        for (int p = 0; p < 4; p++) {
            int i   = p * 256 + tid;
            int row = i >> 3;
            int c4  = i & 7;
            float4 v = *reinterpret_cast<const float4*>(&A[(size_t)(t0 + row) * K + k0 + c4 * 4]);
            As[c4 * 4 + 0][row] = v.x;
            As[c4 * 4 + 1][row] = v.y;
            As[c4 * 4 + 2][row] = v.z;
            As[c4 * 4 + 3][row] = v.w;
        }
        // B tile: 32 k x 128 n
        #pragma unroll
        for (int p = 0; p < 4; p++) {
            int i   = p * 256 + tid;
            int row = i >> 5;
            int c4  = i & 31;
            *reinterpret_cast<float4*>(&Bs[row][c4 * 4]) =
                *reinterpret_cast<const float4*>(&W[(size_t)(k0 + row) * Nout + n0 + c4 * 4]);
        }
        __syncthreads();

        #pragma unroll 16
        for (int kk = 0; kk < BKt; kk++) {
            float4 a0 = *reinterpret_cast<const float4*>(&As[kk][ty * 4]);
            float4 a1 = *reinterpret_cast<const float4*>(&As[kk][64 + ty * 4]);
            ulonglong2 b0 = *reinterpret_cast<const ulonglong2*>(&Bs[kk][tx * 4]);
            ulonglong2 b1 = *reinterpret_cast<const ulonglong2*>(&Bs[kk][64 + tx * 4]);
            unsigned long long bp[4] = { b0.x, b0.y, b1.x, b1.y };
            unsigned long long ap[8];
            ap[0] = pack2(a0.x, a0.x); ap[1] = pack2(a0.y, a0.y);
            ap[2] = pack2(a0.z, a0.z); ap[3] = pack2(a0.w, a0.w);
            ap[4] = pack2(a1.x, a1.x); ap[5] = pack2(a1.y, a1.y);
            ap[6] = pack2(a1.z, a1.z); ap[7] = pack2(a1.w, a1.w);
            #pragma unroll
            for (int mq = 0; mq < 2; mq++)
                #pragma unroll
                for (int m = 0; m < 4; m++)
                    #pragma unroll
                    for (int p = 0; p < 4; p++)
                        acc[mq][m][p] = fma2(ap[mq * 4 + m], bp[p], acc[mq][m][p]);
        }
        __syncthreads();
    }

    // epilogue
    #pragma unroll
    for (int cq = 0; cq < 2; cq++) {
        int col = n0 + cq * 64 + tx * 4;
        float4 b4 = *reinterpret_cast<const float4*>(&bias[col]);
        #pragma unroll
        for (int mq = 0; mq < 2; mq++) {
            #pragma unroll
            for (int m = 0; m < 4; m++) {
                int row = t0 + mq * 64 + ty * 4 + m;
                float2 lo = unpack2(acc[mq][m][cq * 2 + 0]);
                float2 hi = unpack2(acc[mq][m][cq * 2 + 1]);
                float4 v = { lo.x + b4.x, lo.y + b4.y, hi.x + b4.z, hi.y + b4.w };
                if (mode == 1) {
                    float4 r4 = *reinterpret_cast<const float4*>(&res[(size_t)row * Nout + col]);
                    v.x += r4.x; v.y += r4.y; v.z += r4.z; v.w += r4.w;
                } else if (mode == 2) {
                    v.x = fmaxf(v.x, 0.f); v.y = fmaxf(v.y, 0.f);
                    v.z = fmaxf(v.z, 0.f); v.w = fmaxf(v.w, 0.f);
                }
                *reinterpret_cast<float4*>(&C[(size_t)row * Nout + col]) = v;
            }
        }
    }
}

// ---------------- attention on fused qkv buffer ----------------
__global__ __launch_bounds__(128) void attn_kernel(
    const float* __restrict__ QKVb, float* __restrict__ O)
{
    int bh = blockIdx.x;
    int b = bh >> 3;
    int h = bh & 7;
    const size_t rowbase = (size_t)b * NN;
    const size_t hq = h * DKK;

    __shared__ float ksh[NN][DKK];
    __shared__ float vsh[NN][DKK];
    int tid = threadIdx.x;
    for (int i = tid; i < NN * DKK; i += 128) {
        int j = i >> 4, dd = i & 15;
        ksh[j][dd] = QKVb[(rowbase + j) * QKV + EE     + hq + dd];
        vsh[j][dd] = QKVb[(rowbase + j) * QKV + 2 * EE + hq + dd];
    }
    __syncthreads();

    if (tid < NN) {
        float q[DKK];
        #pragma unroll
        for (int dd = 0; dd < DKK; dd++) q[dd] = QKVb[(rowbase + tid) * QKV + hq + dd];
        const float scale = 0.25f;

        float mmax = -1e30f;
        for (int j = 0; j < NN; j++) {
            float sdot = 0.f;
            #pragma unroll
            for (int dd = 0; dd < DKK; dd++) sdot += q[dd] * ksh[j][dd];
            mmax = fmaxf(mmax, sdot * scale);
        }
        float l = 0.f;
        float o[DKK];
        #pragma unroll
        for (int dd = 0; dd < DKK; dd++) o[dd] = 0.f;
        for (int j = 0; j < NN; j++) {
            float sdot = 0.f;
            #pragma unroll
            for (int dd = 0; dd < DKK; dd++) sdot += q[dd] * ksh[j][dd];
            float p = __expf(sdot * scale - mmax);
            l += p;
            #pragma unroll
            for (int dd = 0; dd < DKK; dd++) o[dd] += p * vsh[j][dd];
        }
        float inv = 1.0f / l;
        #pragma unroll
        for (int dd = 0; dd < DKK; dd++)
            O[(rowbase + tid) * EE + hq + dd] = o[dd] * inv;
    }
}

// ---------------- BatchNorm ----------------
#define BN_BLOCKS 256
#define ROWS_PER_BLK (TT / BN_BLOCKS)   // 202
__global__ __launch_bounds__(128) void bn_partial(const float* __restrict__ x,
                                                  float* __restrict__ psum,
                                                  float* __restrict__ psq)
{
    int e = threadIdx.x;
    int blk = blockIdx.x;
    int r0 = blk * ROWS_PER_BLK;
    float s = 0.f, s2 = 0.f;
    #pragma unroll 4
    for (int r = 0; r < ROWS_PER_BLK; r++) {
        float v = x[(size_t)(r0 + r) * EE + e];
        s += v; s2 += v * v;
    }
    psum[blk * EE + e] = s;
    psq [blk * EE + e] = s2;
}

__global__ __launch_bounds__(128) void bn_finalize(const float* __restrict__ psum,
                                                   const float* __restrict__ psq,
                                                   float* __restrict__ mean,
                                                   float* __restrict__ istd)
{
    int e = threadIdx.x;
    float s = 0.f, s2 = 0.f;
    #pragma unroll 8
    for (int i = 0; i < BN_BLOCKS; i++) { s += psum[i * EE + e]; s2 += psq[i * EE + e]; }
    float mu = s / (float)TT;
    float var = s2 / (float)TT - mu * mu;
    mean[e] = mu;
    istd[e] = rsqrtf(var + EPS);
}

__global__ __launch_bounds__(256) void bn_apply(const float* __restrict__ x,
                                                const float* __restrict__ mean,
                                                const float* __restrict__ istd,
                                                const float* __restrict__ g,
                                                const float* __restrict__ be,
                                                float* __restrict__ y)
{
    int idx = blockIdx.x * 256 + threadIdx.x;
    if (idx >= TT * EE) return;
    int e = idx & (EE - 1);
    y[idx] = (x[idx] - mean[e]) * istd[e] * g[e] + be[e];
}

// ---------------- host orchestration ----------------
extern "C" void kernel_launch(void* const* d_in, const int* in_sizes, int n_in,
                              void* d_out, int out_size)
{
    const float* s    = (const float*)d_in[0];
    const int*   dd   = (const int*)  d_in[1];
    const float* e_w  = (const float*)d_in[2];
    const float* e_b  = (const float*)d_in[3];
    const float* ep_w = (const float*)d_in[4];
    const float* ep_b = (const float*)d_in[5];
    const float* Wq   = (const float*)d_in[6];
    const float* bq   = (const float*)d_in[7];
    const float* Wk   = (const float*)d_in[8];
    const float* bk   = (const float*)d_in[9];
    const float* Wv   = (const float*)d_in[10];
    const float* bv   = (const float*)d_in[11];
    const float* Wo   = (const float*)d_in[12];
    const float* bo   = (const float*)d_in[13];
    const float* Wf1  = (const float*)d_in[14];
    const float* bf1  = (const float*)d_in[15];
    const float* Wf2  = (const float*)d_in[16];
    const float* bf2  = (const float*)d_in[17];
    const float* g1   = (const float*)d_in[18];
    const float* be1  = (const float*)d_in[19];
    const float* g2   = (const float*)d_in[20];
    const float* be2  = (const float*)d_in[21];

    float *px, *pqkv, *po, *pt, *ph, *pwq, *pbq, *pps, *pps2, *pmean, *pistd;
    cudaGetSymbolAddress((void**)&px,    g_x);
    cudaGetSymbolAddress((void**)&pqkv,  g_qkv);
    cudaGetSymbolAddress((void**)&po,    g_o);
    cudaGetSymbolAddress((void**)&pt,    g_t);
    cudaGetSymbolAddress((void**)&ph,    g_h);
    cudaGetSymbolAddress((void**)&pwq,   g_wqkv);
    cudaGetSymbolAddress((void**)&pbq,   g_bqkv);
    cudaGetSymbolAddress((void**)&pps,   g_ps);
    cudaGetSymbolAddress((void**)&pps2,  g_ps2);
    cudaGetSymbolAddress((void**)&pmean, g_mean);
    cudaGetSymbolAddress((void**)&pistd, g_istd);

    const int elem_grid = (TT * EE) / 256;
    const dim3 gQKV(QKV / BMt, TT / BMt);   // (3, 404)
    const dim3 gE(EE / BMt, TT / BMt);      // (1, 404)
    const dim3 gF(FF / BMt, TT / BMt);      // (4, 404)

    embed_kernel<<<elem_grid, 256>>>(s, dd, e_w, e_b, ep_w, ep_b, px);
    pack_qkv<<<(3 * EE * QKV + 255) / 256, 256>>>(Wq, Wk, Wv, bq, bk, bv, pwq, pbq);

    for (int i = 0; i < 3; i++) {
        const float* Woi = Wo + (size_t)i * EE * EE;
        const float* W1i = Wf1 + (size_t)i * EE * FF;
        const float* W2i = Wf2 + (size_t)i * FF * EE;

        gemm_ep<<<gQKV, 256>>>(px, pwq + (size_t)i * EE * QKV, pbq + i * QKV,
                               nullptr, pqkv, EE, QKV, 0);
        attn_kernel<<<BB * MM, 128>>>(pqkv, po);

        gemm_ep<<<gE, 256>>>(po, Woi, bo + i * EE, px, pt, EE, EE, 1);
        bn_partial<<<BN_BLOCKS, 128>>>(pt, pps, pps2);
        bn_finalize<<<1, 128>>>(pps, pps2, pmean, pistd);
        bn_apply<<<elem_grid, 256>>>(pt, pmean, pistd, g1 + i * EE, be1 + i * EE, px);

        gemm_ep<<<gF, 256>>>(px, W1i, bf1 + i * FF, nullptr, ph, EE, FF, 2);
        gemm_ep<<<gE, 256>>>(ph, W2i, bf2 + i * EE, px, pt, FF, EE, 1);
        bn_partial<<<BN_BLOCKS, 128>>>(pt, pps, pps2);
        bn_finalize<<<1, 128>>>(pps, pps2, pmean, pistd);
        float* outp = (i == 2) ? (float*)d_out : px;
        bn_apply<<<elem_grid, 256>>>(pt, pmean, pistd, g2 + i * EE, be2 + i * EE, outp);
    }
    (void)in_sizes; (void)n_in; (void)out_size;
}

// round 7
// speedup vs baseline: 1.3479x; 1.2130x over previous
#include <cuda_runtime.h>
#include <cuda_bf16.h>
#include <math.h>

// Problem constants
#define BB   512
#define NN   101
#define EE   128
#define MM   8
#define DKK  16
#define TT   (BB * NN)        // 51712 = 404 * 128
#define FF   (4 * EE)         // 512
#define QKV  (3 * EE)         // 384
#define EPS  1e-5f

// ---------------- device scratch ----------------
__device__ float g_x[TT * EE];
__device__ float g_qkv[TT * QKV];
__device__ float g_o[TT * EE];
__device__ float g_t[TT * EE];
__device__ float g_h[TT * FF];
__device__ float g_wqkv[3 * EE * QKV];
__device__ float g_bqkv[3 * QKV];
__device__ float g_ps [256 * EE];
__device__ float g_ps2[256 * EE];
__device__ float g_scale[EE];
__device__ float g_shift[EE];

// ---------------- f32x2 helpers ----------------
__device__ __forceinline__ unsigned long long fma2(unsigned long long a,
                                                   unsigned long long b,
                                                   unsigned long long c)
{
    unsigned long long d;
    asm("fma.rn.f32x2 %0, %1, %2, %3;" : "=l"(d) : "l"(a), "l"(b), "l"(c));
    return d;
}
__device__ __forceinline__ unsigned long long pack2(float x, float y)
{
    unsigned long long r;
    asm("mov.b64 %0, {%1, %2};" : "=l"(r) : "f"(x), "f"(y));
    return r;
}
__device__ __forceinline__ float2 unpack2(unsigned long long v)
{
    float2 r;
    asm("mov.b64 {%0, %1}, %2;" : "=f"(r.x), "=f"(r.y) : "l"(v));
    return r;
}

// ---------------- embedding ----------------
__global__ void embed_kernel(const float* __restrict__ s, const int* __restrict__ d,
                             const float* __restrict__ e_w, const float* __restrict__ e_b,
                             const float* __restrict__ ep_w, const float* __restrict__ ep_b,
                             float* __restrict__ x)
{
    int idx = blockIdx.x * 256 + threadIdx.x;
    if (idx >= TT * EE) return;
    int e = idx & (EE - 1);
    int t = idx >> 7;
    int n = t % NN;
    int b = t / NN;
    float s0 = s[(b * NN + n) * 2 + 0];
    float s1 = s[(b * NN + n) * 2 + 1];
    float out;
    if (n == 0) {
        out = s0 * ep_w[e] + s1 * ep_w[EE + e] + ep_b[e];
    } else {
        float dd = (float)d[b * NN + n];
        out = s0 * e_w[e] + s1 * e_w[EE + e] + dd * e_w[2 * EE + e] + e_b[e];
    }
    x[idx] = out;
}

// ---------------- pack QKV weights into one [E,384] matrix per layer ----------------
__global__ void pack_qkv(const float* __restrict__ Wq, const float* __restrict__ Wk,
                         const float* __restrict__ Wv, const float* __restrict__ bq,
                         const float* __restrict__ bk, const float* __restrict__ bv,
                         float* __restrict__ wout, float* __restrict__ bout)
{
    int idx = blockIdx.x * 256 + threadIdx.x;
    int total = 3 * EE * QKV;
    if (idx < total) {
        int i = idx / (EE * QKV);
        int r = idx % (EE * QKV);
        int k = r / QKV;
        int j = r % QKV;
        float v;
        if (j < EE)            v = Wq[(size_t)i * EE * EE + k * EE + j];
        else if (j < 2 * EE)   v = Wk[(size_t)i * EE * EE + k * EE + (j - EE)];
        else                   v = Wv[(size_t)i * EE * EE + k * EE + (j - 2 * EE)];
        wout[idx] = v;
    }
    if (idx < 3 * QKV) {
        int i = idx / QKV;
        int j = idx % QKV;
        float v;
        if (j < EE)            v = bq[i * EE + j];
        else if (j < 2 * EE)   v = bk[i * EE + (j - EE)];
        else                   v = bv[i * EE + (j - 2 * EE)];
        bout[idx] = v;
    }
}

// ---------------- 128x128-tile fp32 GEMM, f32x2 inner loop ----------------
// C = affA(A) @ W + bias [+ affR(res) | relu]
// affA: per-K-channel scale/shift on A (nullptr = identity)
// affR: per-N-channel scale/shift on res (mode 1 only)
#define BMt 128
#define BKt 32
#define APAD 4
__global__ __launch_bounds__(256, 2) void gemm_ep(
    const float* __restrict__ A, const float* __restrict__ W,
    const float* __restrict__ bias, const float* __restrict__ res,
    float* __restrict__ C, int K, int Nout, int mode,
    const float* __restrict__ sA, const float* __restrict__ hA,
    const float* __restrict__ sR, const float* __restrict__ hR)
{
    const int t0 = blockIdx.y * BMt;
    const int n0 = blockIdx.x * BMt;
    __shared__ float As[BKt][BMt + APAD];   // transposed [k][m]
    __shared__ float Bs[BKt][BMt];          // [k][n]
    const int tid = threadIdx.x;
    const int tx = tid & 15;
    const int ty = tid >> 4;

    unsigned long long acc[2][4][4];
    #pragma unroll
    for (int mq = 0; mq < 2; mq++)
        #pragma unroll
        for (int m = 0; m < 4; m++)
            #pragma unroll
            for (int p = 0; p < 4; p++)
                acc[mq][m][p] = pack2(0.f, 0.f);

    for (int k0 = 0; k0 < K; k0 += BKt) {
        // A tile: 128 rows x 32 k, optional per-channel affine, transposed into As
        #pragma unroll
        for (int p = 0; p < 4; p++) {
            int i   = p * 256 + tid;
            int row = i >> 3;
            int c4  = i & 7;
            int kc  = k0 + c4 * 4;
            float4 v = *reinterpret_cast<const float4*>(&A[(size_t)(t0 + row) * K + kc]);
            if (sA) {
                float4 sc = *reinterpret_cast<const float4*>(&sA[kc]);
                float4 sh = *reinterpret_cast<const float4*>(&hA[kc]);
                v.x = fmaf(v.x, sc.x, sh.x);
                v.y = fmaf(v.y, sc.y, sh.y);
                v.z = fmaf(v.z, sc.z, sh.z);
                v.w = fmaf(v.w, sc.w, sh.w);
            }
            As[c4 * 4 + 0][row] = v.x;
            As[c4 * 4 + 1][row] = v.y;
            As[c4 * 4 + 2][row] = v.z;
            As[c4 * 4 + 3][row] = v.w;
        }
        // B tile: 32 k x 128 n
        #pragma unroll
        for (int p = 0; p < 4; p++) {
            int i   = p * 256 + tid;
            int row = i >> 5;
            int c4  = i & 31;
            *reinterpret_cast<float4*>(&Bs[row][c4 * 4]) =
                *reinterpret_cast<const float4*>(&W[(size_t)(k0 + row) * Nout + n0 + c4 * 4]);
        }
        __syncthreads();

        #pragma unroll 16
        for (int kk = 0; kk < BKt; kk++) {
            float4 a0 = *reinterpret_cast<const float4*>(&As[kk][ty * 4]);
            float4 a1 = *reinterpret_cast<const float4*>(&As[kk][64 + ty * 4]);
            ulonglong2 b0 = *reinterpret_cast<const ulonglong2*>(&Bs[kk][tx * 4]);
            ulonglong2 b1 = *reinterpret_cast<const ulonglong2*>(&Bs[kk][64 + tx * 4]);
            unsigned long long bp[4] = { b0.x, b0.y, b1.x, b1.y };
            unsigned long long ap[8];
            ap[0] = pack2(a0.x, a0.x); ap[1] = pack2(a0.y, a0.y);
            ap[2] = pack2(a0.z, a0.z); ap[3] = pack2(a0.w, a0.w);
            ap[4] = pack2(a1.x, a1.x); ap[5] = pack2(a1.y, a1.y);
            ap[6] = pack2(a1.z, a1.z); ap[7] = pack2(a1.w, a1.w);
            #pragma unroll
            for (int mq = 0; mq < 2; mq++)
                #pragma unroll
                for (int m = 0; m < 4; m++)
                    #pragma unroll
                    for (int p = 0; p < 4; p++)
                        acc[mq][m][p] = fma2(ap[mq * 4 + m], bp[p], acc[mq][m][p]);
        }
        __syncthreads();
    }

    // epilogue
    #pragma unroll
    for (int cq = 0; cq < 2; cq++) {
        int col = n0 + cq * 64 + tx * 4;
        float4 b4 = *reinterpret_cast<const float4*>(&bias[col]);
        float4 sR4 = {1.f,1.f,1.f,1.f}, hR4 = {0.f,0.f,0.f,0.f};
        if (mode == 1 && sR) {
            sR4 = *reinterpret_cast<const float4*>(&sR[col]);
            hR4 = *reinterpret_cast<const float4*>(&hR[col]);
        }
        #pragma unroll
        for (int mq = 0; mq < 2; mq++) {
            #pragma unroll
            for (int m = 0; m < 4; m++) {
                int row = t0 + mq * 64 + ty * 4 + m;
                float2 lo = unpack2(acc[mq][m][cq * 2 + 0]);
                float2 hi = unpack2(acc[mq][m][cq * 2 + 1]);
                float4 v = { lo.x + b4.x, lo.y + b4.y, hi.x + b4.z, hi.y + b4.w };
                if (mode == 1) {
                    float4 r4 = *reinterpret_cast<const float4*>(&res[(size_t)row * Nout + col]);
                    v.x += fmaf(r4.x, sR4.x, hR4.x) - 0.f;
                    v.y += fmaf(r4.y, sR4.y, hR4.y);
                    v.z += fmaf(r4.z, sR4.z, hR4.z);
                    v.w += fmaf(r4.w, sR4.w, hR4.w);
                } else if (mode == 2) {
                    v.x = fmaxf(v.x, 0.f); v.y = fmaxf(v.y, 0.f);
                    v.z = fmaxf(v.z, 0.f); v.w = fmaxf(v.w, 0.f);
                }
                *reinterpret_cast<float4*>(&C[(size_t)row * Nout + col]) = v;
            }
        }
    }
}

// ---------------- attention v2: single-pass, f32x2 + LDS.128 ----------------
__global__ __launch_bounds__(128) void attn_kernel(
    const float* __restrict__ QKVb, float* __restrict__ O)
{
    int bh = blockIdx.x;
    int b = bh >> 3;
    int h = bh & 7;
    const size_t rowbase = (size_t)b * NN;
    const int hq = h * DKK;

    __shared__ float4 ksh[NN][4];   // 16 floats per key row
    __shared__ float4 vsh[NN][4];
    int tid = threadIdx.x;
    for (int i = tid; i < NN * 4; i += 128) {
        int j = i >> 2, c = i & 3;
        ksh[j][c] = *reinterpret_cast<const float4*>(&QKVb[(rowbase + j) * QKV + EE     + hq + c * 4]);
        vsh[j][c] = *reinterpret_cast<const float4*>(&QKVb[(rowbase + j) * QKV + 2 * EE + hq + c * 4]);
    }
    __syncthreads();

    if (tid < NN) {
        // q pre-scaled by 1/sqrt(dk)
        unsigned long long qp[8];
        #pragma unroll
        for (int c = 0; c < 4; c++) {
            float4 q4 = *reinterpret_cast<const float4*>(&QKVb[(rowbase + tid) * QKV + hq + c * 4]);
            qp[c * 2 + 0] = pack2(q4.x * 0.25f, q4.y * 0.25f);
            qp[c * 2 + 1] = pack2(q4.z * 0.25f, q4.w * 0.25f);
        }
        const unsigned long long z2 = pack2(0.f, 0.f);
        unsigned long long oa[8];
        #pragma unroll
        for (int c = 0; c < 8; c++) oa[c] = z2;
        float l = 0.f;

        for (int j = 0; j < NN; j++) {
            const ulonglong2* kr = reinterpret_cast<const ulonglong2*>(&ksh[j][0]);
            ulonglong2 k0 = kr[0], k1 = kr[1];
            unsigned long long c0 = fma2(qp[0], k0.x, z2);
            unsigned long long c1 = fma2(qp[1], k0.y, z2);
            c0 = fma2(qp[2], k1.x, c0);
            c1 = fma2(qp[3], k1.y, c1);
            const ulonglong2* kr2 = reinterpret_cast<const ulonglong2*>(&ksh[j][2]);
            ulonglong2 k2 = kr2[0], k3 = kr2[1];
            c0 = fma2(qp[4], k2.x, c0);
            c1 = fma2(qp[5], k2.y, c1);
            c0 = fma2(qp[6], k3.x, c0);
            c1 = fma2(qp[7], k3.y, c1);
            float2 f0 = unpack2(c0), f1 = unpack2(c1);
            float sdot = (f0.x + f0.y) + (f1.x + f1.y);
            float p = __expf(sdot);
            l += p;
            unsigned long long pp = pack2(p, p);
            const ulonglong2* vr = reinterpret_cast<const ulonglong2*>(&vsh[j][0]);
            ulonglong2 v0 = vr[0], v1 = vr[1];
            oa[0] = fma2(pp, v0.x, oa[0]);
            oa[1] = fma2(pp, v0.y, oa[1]);
            oa[2] = fma2(pp, v1.x, oa[2]);
            oa[3] = fma2(pp, v1.y, oa[3]);
            const ulonglong2* vr2 = reinterpret_cast<const ulonglong2*>(&vsh[j][2]);
            ulonglong2 v2 = vr2[0], v3 = vr2[1];
            oa[4] = fma2(pp, v2.x, oa[4]);
            oa[5] = fma2(pp, v2.y, oa[5]);
            oa[6] = fma2(pp, v3.x, oa[6]);
            oa[7] = fma2(pp, v3.y, oa[7]);
        }
        float inv = 1.0f / l;
        float* orow = &O[(rowbase + tid) * EE + hq];
        #pragma unroll
        for (int c = 0; c < 4; c++) {
            float2 lo = unpack2(oa[c * 2 + 0]);
            float2 hi = unpack2(oa[c * 2 + 1]);
            float4 v = { lo.x * inv, lo.y * inv, hi.x * inv, hi.y * inv };
            *reinterpret_cast<float4*>(&orow[c * 4]) = v;
        }
    }
}

// ---------------- BatchNorm stats ----------------
#define BN_BLOCKS 256
#define ROWS_PER_BLK (TT / BN_BLOCKS)   // 202
__global__ __launch_bounds__(128) void bn_partial(const float* __restrict__ x,
                                                  float* __restrict__ psum,
                                                  float* __restrict__ psq)
{
    int e = threadIdx.x;
    int blk = blockIdx.x;
    int r0 = blk * ROWS_PER_BLK;
    float s = 0.f, s2 = 0.f;
    #pragma unroll 4
    for (int r = 0; r < ROWS_PER_BLK; r++) {
        float v = x[(size_t)(r0 + r) * EE + e];
        s += v; s2 += v * v;
    }
    psum[blk * EE + e] = s;
    psq [blk * EE + e] = s2;
}

// scale = g*rsqrt(var+eps), shift = be - mu*scale
__global__ __launch_bounds__(128) void bn_finalize(const float* __restrict__ psum,
                                                   const float* __restrict__ psq,
                                                   const float* __restrict__ g,
                                                   const float* __restrict__ be,
                                                   float* __restrict__ scale,
                                                   float* __restrict__ shift)
{
    int e = threadIdx.x;
    float s = 0.f, s2 = 0.f;
    #pragma unroll 8
    for (int i = 0; i < BN_BLOCKS; i++) { s += psum[i * EE + e]; s2 += psq[i * EE + e]; }
    float mu = s / (float)TT;
    float var = s2 / (float)TT - mu * mu;
    float sc = rsqrtf(var + EPS) * g[e];
    scale[e] = sc;
    shift[e] = be[e] - mu * sc;
}

__global__ __launch_bounds__(256) void bn_apply_final(const float* __restrict__ x,
                                                      const float* __restrict__ scale,
                                                      const float* __restrict__ shift,
                                                      float* __restrict__ y)
{
    int idx = blockIdx.x * 256 + threadIdx.x;
    if (idx >= TT * EE) return;
    int e = idx & (EE - 1);
    y[idx] = fmaf(x[idx], scale[e], shift[e]);
}

// ---------------- host orchestration ----------------
extern "C" void kernel_launch(void* const* d_in, const int* in_sizes, int n_in,
                              void* d_out, int out_size)
{
    const float* s    = (const float*)d_in[0];
    const int*   dd   = (const int*)  d_in[1];
    const float* e_w  = (const float*)d_in[2];
    const float* e_b  = (const float*)d_in[3];
    const float* ep_w = (const float*)d_in[4];
    const float* ep_b = (const float*)d_in[5];
    const float* Wq   = (const float*)d_in[6];
    const float* bq   = (const float*)d_in[7];
    const float* Wk   = (const float*)d_in[8];
    const float* bk   = (const float*)d_in[9];
    const float* Wv   = (const float*)d_in[10];
    const float* bv   = (const float*)d_in[11];
    const float* Wo   = (const float*)d_in[12];
    const float* bo   = (const float*)d_in[13];
    const float* Wf1  = (const float*)d_in[14];
    const float* bf1  = (const float*)d_in[15];
    const float* Wf2  = (const float*)d_in[16];
    const float* bf2  = (const float*)d_in[17];
    const float* g1   = (const float*)d_in[18];
    const float* be1  = (const float*)d_in[19];
    const float* g2   = (const float*)d_in[20];
    const float* be2  = (const float*)d_in[21];

    float *px, *pqkv, *po, *pt, *ph, *pwq, *pbq, *pps, *pps2, *pscale, *pshift;
    cudaGetSymbolAddress((void**)&px,     g_x);
    cudaGetSymbolAddress((void**)&pqkv,   g_qkv);
    cudaGetSymbolAddress((void**)&po,     g_o);
    cudaGetSymbolAddress((void**)&pt,     g_t);
    cudaGetSymbolAddress((void**)&ph,     g_h);
    cudaGetSymbolAddress((void**)&pwq,    g_wqkv);
    cudaGetSymbolAddress((void**)&pbq,    g_bqkv);
    cudaGetSymbolAddress((void**)&pps,    g_ps);
    cudaGetSymbolAddress((void**)&pps2,   g_ps2);
    cudaGetSymbolAddress((void**)&pscale, g_scale);
    cudaGetSymbolAddress((void**)&pshift, g_shift);

    const int elem_grid = (TT * EE) / 256;
    const dim3 gQKV(QKV / BMt, TT / BMt);   // (3, 404)
    const dim3 gE(EE / BMt, TT / BMt);      // (1, 404)
    const dim3 gF(FF / BMt, TT / BMt);      // (4, 404)

    embed_kernel<<<elem_grid, 256>>>(s, dd, e_w, e_b, ep_w, ep_b, px);
    pack_qkv<<<(3 * EE * QKV + 255) / 256, 256>>>(Wq, Wk, Wv, bq, bk, bv, pwq, pbq);

    const float* curS = nullptr;   // pending bn affine on the "current x" buffer (px)
    const float* curH = nullptr;

    for (int i = 0; i < 3; i++) {
        const float* Woi = Wo + (size_t)i * EE * EE;
        const float* W1i = Wf1 + (size_t)i * EE * FF;
        const float* W2i = Wf2 + (size_t)i * FF * EE;

        // qkv = bn(x) @ Wqkv + b
        gemm_ep<<<gQKV, 256>>>(px, pwq + (size_t)i * EE * QKV, pbq + i * QKV,
                               nullptr, pqkv, EE, QKV, 0, curS, curH, nullptr, nullptr);
        attn_kernel<<<BB * MM, 128>>>(pqkv, po);

        // t1 = o @ Wo + bo + bn(x)
        gemm_ep<<<gE, 256>>>(po, Woi, bo + i * EE, px, pt, EE, EE, 1,
                             nullptr, nullptr, curS, curH);
        bn_partial<<<BN_BLOCKS, 128>>>(pt, pps, pps2);
        bn_finalize<<<1, 128>>>(pps, pps2, g1 + i * EE, be1 + i * EE, pscale, pshift);

        // h = relu(bn1(t1) @ Wf1 + bf1)
        gemm_ep<<<gF, 256>>>(pt, W1i, bf1 + i * FF, nullptr, ph, EE, FF, 2,
                             pscale, pshift, nullptr, nullptr);
        // t2 = h @ Wf2 + bf2 + bn1(t1)   -> write into px (old cur is dead)
        gemm_ep<<<gE, 256>>>(ph, W2i, bf2 + i * EE, pt, px, FF, EE, 1,
                             nullptr, nullptr, pscale, pshift);
        bn_partial<<<BN_BLOCKS, 128>>>(px, pps, pps2);
        bn_finalize<<<1, 128>>>(pps, pps2, g2 + i * EE, be2 + i * EE, pscale, pshift);
        curS = pscale; curH = pshift;
    }
    bn_apply_final<<<elem_grid, 256>>>(px, pscale, pshift, (float*)d_out);
    (void)in_sizes; (void)n_in; (void)out_size;
}